// round 4
// baseline (speedup 1.0000x reference)
#include <cuda_runtime.h>
#include <cstdint>

#define NUM_USERS 100000
#define NUM_ITEMS 100000
#define N_NODES   200000
#define EMB       64
#define N_EDGES   3200000
#define VEC_TOTAL (N_NODES * (EMB / 4))   // 3,200,000 float4s per node-buffer

// Ping-pong propagation buffers (51.2 MB each). Static device globals: the
// only allocation-free scratch mechanism allowed by the harness.
__device__ float g_buf0[(size_t)N_NODES * EMB];
__device__ float g_buf1[(size_t)N_NODES * EMB];

// ---------------------------------------------------------------------------
// Init: buf0 = concat(user_emb, item_emb); buf1 = 0 (layer-0 scatter dst);
//       out  = 0 (accumulator).
// ---------------------------------------------------------------------------
__global__ void k_init(const float4* __restrict__ user,
                       const float4* __restrict__ item,
                       float4* __restrict__ out)
{
    int i = blockIdx.x * blockDim.x + threadIdx.x;
    if (i >= VEC_TOTAL) return;
    const int usz = NUM_USERS * (EMB / 4);
    float4 v = (i < usz) ? __ldg(user + i) : __ldg(item + (i - usz));
    reinterpret_cast<float4*>(g_buf0)[i] = v;
    float4 z = make_float4(0.f, 0.f, 0.f, 0.f);
    reinterpret_cast<float4*>(g_buf1)[i] = z;
    out[i] = z;
}

// ---------------------------------------------------------------------------
// Scatter (SpMM): dst[row] += w * src[col], 16 threads per edge, one float4
// each. Vector RED (sm_90+) keeps it at 1 instruction / 16B / lane.
// layer even: src = buf0, dst = buf1.   layer odd: src = buf1, dst = buf0.
// ---------------------------------------------------------------------------
__global__ void __launch_bounds__(256)
k_scatter(const int* __restrict__ row,
          const int* __restrict__ col,
          const float* __restrict__ w,
          int layer)
{
    long long tid = (long long)blockIdx.x * blockDim.x + threadIdx.x;
    int e = (int)(tid >> 4);
    if (e >= N_EDGES) return;
    int t = (int)(tid & 15);

    const float* src = (layer & 1) ? g_buf1 : g_buf0;
    float*       dst = (layer & 1) ? g_buf0 : g_buf1;

    int   c  = __ldg(col + e);
    int   r  = __ldg(row + e);
    float ww = __ldg(w + e);

    float4 v = __ldg(reinterpret_cast<const float4*>(src + (size_t)c * EMB) + t);

    float* p = dst + (size_t)r * EMB + t * 4;
    asm volatile("red.global.add.v4.f32 [%0], {%1,%2,%3,%4};"
                 :: "l"(p), "f"(v.x * ww), "f"(v.y * ww),
                    "f"(v.z * ww), "f"(v.w * ww)
                 : "memory");
}

// ---------------------------------------------------------------------------
// Combine: out += layer_result * (1/3); zero the buffer that becomes the
// NEXT layer's scatter destination (skipped on the last layer).
// layer_result = dst(layer); zero target = src(layer).
// ---------------------------------------------------------------------------
__global__ void __launch_bounds__(256)
k_combine(float4* __restrict__ out, int layer, int do_zero)
{
    int i = blockIdx.x * blockDim.x + threadIdx.x;
    if (i >= VEC_TOTAL) return;

    float4* dst4 = reinterpret_cast<float4*>((layer & 1) ? g_buf0 : g_buf1);
    float4* src4 = reinterpret_cast<float4*>((layer & 1) ? g_buf1 : g_buf0);

    const float inv3 = 1.0f / 3.0f;
    float4 d = dst4[i];
    float4 o = out[i];
    o.x += d.x * inv3;
    o.y += d.y * inv3;
    o.z += d.z * inv3;
    o.w += d.w * inv3;
    out[i] = o;

    if (do_zero) {
        src4[i] = make_float4(0.f, 0.f, 0.f, 0.f);
    }
}

// ---------------------------------------------------------------------------
// Launch. Inputs (metadata order):
//   d_in[0] user_emb  f32 [100000*64]
//   d_in[1] item_emb  f32 [100000*64]
//   d_in[2] edge_w    f32 [3200000]
//   d_in[3] edge_row  i32 [3200000]
//   d_in[4] edge_col  i32 [3200000]
// d_out: f32 [200000*64] = concat(user_all, item_all) = acc / 3.
// ---------------------------------------------------------------------------
extern "C" void kernel_launch(void* const* d_in, const int* in_sizes, int n_in,
                              void* d_out, int out_size)
{
    const float4* user = (const float4*)d_in[0];
    const float4* item = (const float4*)d_in[1];
    const float*  ew   = (const float*)d_in[2];
    const int*    erow = (const int*)d_in[3];
    const int*    ecol = (const int*)d_in[4];
    float4*       out  = (float4*)d_out;

    const int BLK = 256;
    const int grid_vec = (VEC_TOTAL + BLK - 1) / BLK;                       // 12500
    const long long sc_threads = (long long)N_EDGES * 16;
    const int grid_sc = (int)((sc_threads + BLK - 1) / BLK);                // 200000

    k_init<<<grid_vec, BLK>>>(user, item, out);

    for (int layer = 0; layer < 3; ++layer) {
        k_scatter<<<grid_sc, BLK>>>(erow, ecol, ew, layer);
        k_combine<<<grid_vec, BLK>>>(out, layer, (layer < 2) ? 1 : 0);
    }
}

// round 5
// speedup vs baseline: 2.0634x; 2.0634x over previous
#include <cuda_runtime.h>
#include <cstdint>

#define NUM_USERS 100000
#define NUM_ITEMS 100000
#define N_NODES   200000
#define EMB       64
#define N_EDGES   3200000
#define SCAN_BLK  1024
#define N_SCAN_BLKS ((N_NODES + SCAN_BLK - 1) / SCAN_BLK)   // 196

// ---------------------------------------------------------------------------
// Static device scratch (allocation-free per harness rules).
// ---------------------------------------------------------------------------
__device__ float g_buf0[(size_t)N_NODES * EMB];   // layer-1 input  (51.2 MB)
__device__ float g_buf1[(size_t)N_NODES * EMB];   // layer-2 input  (51.2 MB)
__device__ int2  g_csr[N_EDGES];                  // (col, w-bits) grouped by row (25.6 MB)
__device__ int   g_cnt[N_NODES];                  // per-row degree
__device__ int   g_rowstart[N_NODES + 1];         // CSR offsets
__device__ int   g_cursor[N_NODES];               // fill cursors
__device__ int   g_blksums[N_SCAN_BLKS];          // scan partials

// ---------------------------------------------------------------------------
// CSR build: zero -> count -> 3-step scan -> fill
// ---------------------------------------------------------------------------
__global__ void k_zero()
{
    int i = blockIdx.x * blockDim.x + threadIdx.x;
    if (i < N_NODES) g_cnt[i] = 0;
}

__global__ void __launch_bounds__(256) k_count(const int* __restrict__ row)
{
    int e = blockIdx.x * blockDim.x + threadIdx.x;
    if (e < N_EDGES) atomicAdd(&g_cnt[__ldg(row + e)], 1);
}

__global__ void __launch_bounds__(SCAN_BLK) k_scan1()
{
    __shared__ int s[SCAN_BLK];
    int t = threadIdx.x;
    int i = blockIdx.x * SCAN_BLK + t;
    int v = (i < N_NODES) ? g_cnt[i] : 0;
    s[t] = v;
    __syncthreads();
    #pragma unroll
    for (int off = 1; off < SCAN_BLK; off <<= 1) {
        int add = (t >= off) ? s[t - off] : 0;
        __syncthreads();
        s[t] += add;
        __syncthreads();
    }
    if (i < N_NODES) g_rowstart[i] = s[t] - v;          // exclusive within block
    if (t == SCAN_BLK - 1) g_blksums[blockIdx.x] = s[t]; // block total
}

__global__ void k_scan2()
{
    if (threadIdx.x == 0) {
        int run = 0;
        for (int b = 0; b < N_SCAN_BLKS; ++b) {
            int t = g_blksums[b];
            g_blksums[b] = run;
            run += t;
        }
    }
}

__global__ void k_scan3()
{
    int i = blockIdx.x * blockDim.x + threadIdx.x;
    if (i < N_NODES) {
        int v = g_rowstart[i] + g_blksums[i >> 10];
        g_rowstart[i] = v;
        g_cursor[i]   = v;
    }
    if (i == 0) g_rowstart[N_NODES] = N_EDGES;
}

__global__ void __launch_bounds__(256)
k_fill(const int* __restrict__ row, const int* __restrict__ col,
       const float* __restrict__ w)
{
    int e = blockIdx.x * blockDim.x + threadIdx.x;
    if (e >= N_EDGES) return;
    int r   = __ldg(row + e);
    int pos = atomicAdd(&g_cursor[r], 1);
    g_csr[pos] = make_int2(__ldg(col + e), __float_as_int(__ldg(w + e)));
}

// ---------------------------------------------------------------------------
// Gather SpMM: one warp per destination row, float2 per lane (EMB=64).
// Batches 4 edges per iteration -> 4 independent LDG.64 per warp (MLP=4).
// Epilogue fuses dst-buffer write (layers 0,1) and out accumulation (/3).
// ---------------------------------------------------------------------------
template<int LAYER>
__device__ __forceinline__ float2 ld_src(int c, int lane,
                                         const float2* __restrict__ user,
                                         const float2* __restrict__ item)
{
    if (LAYER == 0) {
        return (c < NUM_USERS)
            ? __ldg(user + (size_t)c * 32 + lane)
            : __ldg(item + (size_t)(c - NUM_USERS) * 32 + lane);
    } else if (LAYER == 1) {
        return reinterpret_cast<const float2*>(g_buf0)[(size_t)c * 32 + lane];
    } else {
        return reinterpret_cast<const float2*>(g_buf1)[(size_t)c * 32 + lane];
    }
}

template<int LAYER>
__global__ void __launch_bounds__(256)
k_gather(const float2* __restrict__ user, const float2* __restrict__ item,
         float2* __restrict__ out)
{
    int gwarp = (blockIdx.x * blockDim.x + threadIdx.x) >> 5;
    int lane  = threadIdx.x & 31;
    if (gwarp >= N_NODES) return;
    const int row   = gwarp;
    const int start = __ldg(&g_rowstart[row]);
    const int end   = __ldg(&g_rowstart[row + 1]);

    float ax = 0.f, ay = 0.f;
    int j = start;
    // 4-edge batches: independent gathers before the accumulate chain.
    for (; j + 4 <= end; j += 4) {
        int2 m0 = __ldg(&g_csr[j + 0]);
        int2 m1 = __ldg(&g_csr[j + 1]);
        int2 m2 = __ldg(&g_csr[j + 2]);
        int2 m3 = __ldg(&g_csr[j + 3]);
        float2 v0 = ld_src<LAYER>(m0.x, lane, user, item);
        float2 v1 = ld_src<LAYER>(m1.x, lane, user, item);
        float2 v2 = ld_src<LAYER>(m2.x, lane, user, item);
        float2 v3 = ld_src<LAYER>(m3.x, lane, user, item);
        float w0 = __int_as_float(m0.y), w1 = __int_as_float(m1.y);
        float w2 = __int_as_float(m2.y), w3 = __int_as_float(m3.y);
        ax += w0 * v0.x; ay += w0 * v0.y;
        ax += w1 * v1.x; ay += w1 * v1.y;
        ax += w2 * v2.x; ay += w2 * v2.y;
        ax += w3 * v3.x; ay += w3 * v3.y;
    }
    for (; j < end; ++j) {
        int2 m = __ldg(&g_csr[j]);
        float2 v = ld_src<LAYER>(m.x, lane, user, item);
        float ww = __int_as_float(m.y);
        ax += ww * v.x; ay += ww * v.y;
    }

    const size_t oidx = (size_t)row * 32 + lane;
    float2 res = make_float2(ax, ay);

    if (LAYER == 0) reinterpret_cast<float2*>(g_buf0)[oidx] = res;
    if (LAYER == 1) reinterpret_cast<float2*>(g_buf1)[oidx] = res;

    const float inv3 = 1.0f / 3.0f;
    if (LAYER == 0) {
        out[oidx] = make_float2(ax * inv3, ay * inv3);
    } else {
        float2 o = out[oidx];
        o.x += ax * inv3;
        o.y += ay * inv3;
        out[oidx] = o;
    }
}

// ---------------------------------------------------------------------------
// Launch. Inputs (metadata order):
//   d_in[0] user_emb f32 [100000*64]   d_in[1] item_emb f32 [100000*64]
//   d_in[2] edge_w   f32 [3.2M]        d_in[3] edge_row i32   d_in[4] edge_col i32
// d_out: f32 [200000*64] = acc / 3.
// ---------------------------------------------------------------------------
extern "C" void kernel_launch(void* const* d_in, const int* in_sizes, int n_in,
                              void* d_out, int out_size)
{
    const float2* user = (const float2*)d_in[0];
    const float2* item = (const float2*)d_in[1];
    const float*  ew   = (const float*)d_in[2];
    const int*    erow = (const int*)d_in[3];
    const int*    ecol = (const int*)d_in[4];
    float2*       out  = (float2*)d_out;

    const int BLK = 256;
    const int grid_nodes = (N_NODES + BLK - 1) / BLK;        // 782
    const int grid_edges = (N_EDGES + BLK - 1) / BLK;        // 12500
    const int grid_gather = (N_NODES * 32 + BLK - 1) / BLK;  // 25000 (warp/row)

    // CSR build (once; reused by all 3 layers)
    k_zero <<<grid_nodes, BLK>>>();
    k_count<<<grid_edges, BLK>>>(erow);
    k_scan1<<<N_SCAN_BLKS, SCAN_BLK>>>();
    k_scan2<<<1, 32>>>();
    k_scan3<<<grid_nodes, BLK>>>();
    k_fill <<<grid_edges, BLK>>>(erow, ecol, ew);

    // 3 pull-style SpMM layers with fused accumulation
    k_gather<0><<<grid_gather, BLK>>>(user, item, out);
    k_gather<1><<<grid_gather, BLK>>>(user, item, out);
    k_gather<2><<<grid_gather, BLK>>>(user, item, out);
}